// round 9
// baseline (speedup 1.0000x reference)
#include <cuda_runtime.h>
#include <cuda_bf16.h>
#include <cstdint>

#define N_NODES 50000
#define N_EDGES 800000
#define D 128
#define NT 391            // ceil(N_NODES/128)
#define SCAN_BLOCKS 196   // 196*256 = 50176 >= N_NODES

// ==================== scratch (no allocations allowed) ====================
__device__ int g_hist[N_NODES];
__device__ int g_cursor[N_NODES];
__device__ int g_rowstart[N_NODES + 1];
__device__ int g_col[N_EDGES];
__device__ int g_blocksum[SCAN_BLOCKS];
__device__ int g_blockoff[SCAN_BLOCKS];
// pre-swizzled bf16 W^T images: [matrix 0..5][hi=0/lo=1][2 kchunks x 128 x 64]
__device__ __align__(128) __nv_bfloat16 g_Bimg[6][2][D * D];
// node-feature tile images: [set][hi/lo][tile*16384 bf16] (32KB per tile: kc0|kc1)
__device__ __align__(128) __nv_bfloat16 g_imgA[2][2][(size_t)NT * 16384];
// hneigh tile images: [hi/lo]
__device__ __align__(128) __nv_bfloat16 g_imgN[2][(size_t)NT * 16384];

// XOR swizzle: row-major 64 bf16 per row (128B), 8 chunks of 16B, chunk ^= row&7
__device__ __forceinline__ uint32_t swz(uint32_t row, uint32_t kbyte) {
    return row * 128u + ((((kbyte >> 4) ^ (row & 7u)) << 4) | (kbyte & 15u));
}

__device__ __forceinline__ uint32_t smem_u32(const void* p) {
    uint32_t a;
    asm("{ .reg .u64 t; cvta.to.shared.u64 t, %1; cvt.u32.u64 %0, t; }" : "=r"(a) : "l"(p));
    return a;
}
__device__ __forceinline__ void cp_async16(uint32_t saddr, const void* gptr) {
    asm volatile("cp.async.cg.shared.global [%0], [%1], 16;" :: "r"(saddr), "l"(gptr));
}
#define CP_COMMIT() asm volatile("cp.async.commit_group;" ::: "memory")
#define CP_WAIT(n)  asm volatile("cp.async.wait_group %0;" :: "n"(n) : "memory")

__device__ __forceinline__ void ldsm_x4(uint32_t addr, uint32_t& r0, uint32_t& r1,
                                        uint32_t& r2, uint32_t& r3) {
    asm volatile("ldmatrix.sync.aligned.m8n8.x4.shared.b16 {%0,%1,%2,%3}, [%4];"
                 : "=r"(r0), "=r"(r1), "=r"(r2), "=r"(r3) : "r"(addr));
}
__device__ __forceinline__ void mma_16816(float* c, const uint32_t* a, const uint32_t* b) {
    asm volatile(
        "mma.sync.aligned.m16n8k16.row.col.f32.bf16.bf16.f32 "
        "{%0,%1,%2,%3}, {%4,%5,%6,%7}, {%8,%9}, {%0,%1,%2,%3};"
        : "+f"(c[0]), "+f"(c[1]), "+f"(c[2]), "+f"(c[3])
        : "r"(a[0]), "r"(a[1]), "r"(a[2]), "r"(a[3]), "r"(b[0]), "r"(b[1]));
}
// split x,y into packed bf16x2 hi + bf16x2 lo(residual)
__device__ __forceinline__ void split2(float x, float y, uint32_t& hp, uint32_t& lp) {
    __nv_bfloat16 hx = __float2bfloat16(x);
    __nv_bfloat16 hy = __float2bfloat16(y);
    __nv_bfloat16 lx = __float2bfloat16(x - __bfloat162float(hx));
    __nv_bfloat16 ly = __float2bfloat16(y - __bfloat162float(hy));
    hp = (uint32_t)__bfloat16_as_ushort(hx) | ((uint32_t)__bfloat16_as_ushort(hy) << 16);
    lp = (uint32_t)__bfloat16_as_ushort(lx) | ((uint32_t)__bfloat16_as_ushort(ly) << 16);
}
// bf16 (low/high half of u32) -> fp32 is a pure shift
__device__ __forceinline__ float bflo(uint32_t u) { return __uint_as_float(u << 16); }
__device__ __forceinline__ float bfhi(uint32_t u) { return __uint_as_float(u & 0xffff0000u); }

// ==================== CSR build ====================
__global__ void hist_kernel(const int* __restrict__ dst) {
    int e = blockIdx.x * blockDim.x + threadIdx.x;
    if (e < N_EDGES) atomicAdd(&g_hist[dst[e]], 1);
}

__global__ void scan_local() {
    __shared__ int sh[256];
    int t = threadIdx.x;
    int idx = blockIdx.x * 256 + t;
    int v = (idx < N_NODES) ? g_hist[idx] : 0;
    sh[t] = v;
    __syncthreads();
    #pragma unroll
    for (int off = 1; off < 256; off <<= 1) {
        int x = sh[t];
        int add = (t >= off) ? sh[t - off] : 0;
        __syncthreads();
        sh[t] = x + add;
        __syncthreads();
    }
    if (idx < N_NODES) g_rowstart[idx] = sh[t] - v;
    if (t == 255) g_blocksum[blockIdx.x] = sh[255];
}

__global__ void scan_blocks() {
    __shared__ int sh[256];
    int t = threadIdx.x;
    int v = (t < SCAN_BLOCKS) ? g_blocksum[t] : 0;
    sh[t] = v;
    __syncthreads();
    #pragma unroll
    for (int off = 1; off < 256; off <<= 1) {
        int x = sh[t];
        int add = (t >= off) ? sh[t - off] : 0;
        __syncthreads();
        sh[t] = x + add;
        __syncthreads();
    }
    if (t < SCAN_BLOCKS) g_blockoff[t] = sh[t] - v;
    if (t == 255) g_rowstart[N_NODES] = sh[255];
}

__global__ void scan_apply() {
    int idx = blockIdx.x * 256 + threadIdx.x;
    if (idx < N_NODES) {
        int r = g_rowstart[idx] + g_blockoff[blockIdx.x];
        g_rowstart[idx] = r;
        g_cursor[idx] = r;
    }
}

__global__ void fill_kernel(const int* __restrict__ src, const int* __restrict__ dst) {
    int e = blockIdx.x * blockDim.x + threadIdx.x;
    if (e < N_EDGES) {
        int pos = atomicAdd(&g_cursor[dst[e]], 1);
        g_col[pos] = src[e];
    }
}

// ==================== features fp32 -> tile images (set 0) ====================
__global__ void convert_features(const float* __restrict__ h, char* __restrict__ hi,
                                 char* __restrict__ lo) {
    int tile = blockIdx.x;
    int m0 = tile * 128;
    #pragma unroll 4
    for (int it = 0; it < 32; ++it) {
        int idx = threadIdx.x + it * 256;
        int row = idx >> 6;
        int k = (idx & 63) * 2;
        int gm = m0 + row;
        float2 a = (gm < N_NODES) ? *reinterpret_cast<const float2*>(h + (size_t)gm * D + k)
                                  : make_float2(0.f, 0.f);
        uint32_t hp, lp;
        split2(a.x, a.y, hp, lp);
        uint32_t off = (uint32_t)tile * 32768u + (uint32_t)(k >> 6) * 16384u
                     + swz((uint32_t)row, (uint32_t)((k & 63) * 2));
        *(uint32_t*)(hi + off) = hp;
        *(uint32_t*)(lo + off) = lp;
    }
}

// ==================== aggregation: warp/node, gathers bf16 hi/lo images ===========
__global__ void aggregate_kernel(const char* __restrict__ ahi, const char* __restrict__ alo,
                                 char* __restrict__ nhi, char* __restrict__ nlo) {
    int node = (blockIdx.x * blockDim.x + threadIdx.x) >> 5;
    int lane = threadIdx.x & 31;
    if (node >= N_NODES) return;
    int beg = g_rowstart[node];
    int end = g_rowstart[node + 1];

    const int k0 = lane * 4;                                   // elements k0..k0+3
    const uint32_t laneoff = (uint32_t)(k0 >> 6) * 16384u;     // k-chunk
    const uint32_t kb = (uint32_t)((k0 & 63) * 2);             // byte within row

    float4 acc = make_float4(0.f, 0.f, 0.f, 0.f);
    int i = beg;
    for (; i + 2 <= end; i += 2) {
        int s0 = g_col[i + 0];
        int s1 = g_col[i + 1];
        uint32_t o0 = (uint32_t)(s0 >> 7) * 32768u + laneoff + swz((uint32_t)(s0 & 127), kb);
        uint32_t o1 = (uint32_t)(s1 >> 7) * 32768u + laneoff + swz((uint32_t)(s1 & 127), kb);
        uint2 h0 = *(const uint2*)(ahi + o0);
        uint2 l0 = *(const uint2*)(alo + o0);
        uint2 h1 = *(const uint2*)(ahi + o1);
        uint2 l1 = *(const uint2*)(alo + o1);
        acc.x += (bflo(h0.x) + bflo(l0.x)) + (bflo(h1.x) + bflo(l1.x));
        acc.y += (bfhi(h0.x) + bfhi(l0.x)) + (bfhi(h1.x) + bfhi(l1.x));
        acc.z += (bflo(h0.y) + bflo(l0.y)) + (bflo(h1.y) + bflo(l1.y));
        acc.w += (bfhi(h0.y) + bfhi(l0.y)) + (bfhi(h1.y) + bfhi(l1.y));
    }
    for (; i < end; ++i) {
        int s = g_col[i];
        uint32_t o = (uint32_t)(s >> 7) * 32768u + laneoff + swz((uint32_t)(s & 127), kb);
        uint2 h0 = *(const uint2*)(ahi + o);
        uint2 l0 = *(const uint2*)(alo + o);
        acc.x += bflo(h0.x) + bflo(l0.x);
        acc.y += bfhi(h0.x) + bfhi(l0.x);
        acc.z += bflo(h0.y) + bflo(l0.y);
        acc.w += bfhi(h0.y) + bfhi(l0.y);
    }
    float sc = 1.0f / fmaxf((float)(end - beg), 1.0f);
    acc.x *= sc; acc.y *= sc; acc.z *= sc; acc.w *= sc;

    int tile = node >> 7;
    int row = node & 127;
    uint32_t off = (uint32_t)tile * 32768u + laneoff + swz((uint32_t)row, kb);
    uint32_t h0, l0, h1, l1;
    split2(acc.x, acc.y, h0, l0);
    split2(acc.z, acc.w, h1, l1);
    *(uint2*)(nhi + off) = make_uint2(h0, h1);
    *(uint2*)(nlo + off) = make_uint2(l0, l1);
}

// ==================== weight prep ====================
__global__ void prep_weights(const float* W0s, const float* W0n, const float* W1s,
                             const float* W1n, const float* W2s, const float* W2n) {
    const float* Wp[6] = {W0s, W0n, W1s, W1n, W2s, W2n};
    int mat = blockIdx.x >> 3;
    int sub = blockIdx.x & 7;
    const float* W = Wp[mat];
    char* hi = (char*)g_Bimg[mat][0];
    char* lo = (char*)g_Bimg[mat][1];
    for (int t = threadIdx.x; t < 1024; t += blockDim.x) {
        int idx = sub * 1024 + t;
        int n = idx >> 6;
        int k = (idx & 63) * 2;
        float a0 = W[(size_t)k * D + n];
        float a1 = W[(size_t)(k + 1) * D + n];
        uint32_t hp, lp;
        split2(a0, a1, hp, lp);
        uint32_t off = (uint32_t)(k >> 6) * 16384u + swz((uint32_t)n, (uint32_t)((k & 63) * 2));
        *(uint32_t*)(hi + off) = hp;
        *(uint32_t*)(lo + off) = lp;
    }
}

// ==================== HMMA dual GEMM, 12x32KB phases, 3-stage pipeline, occ=2 ======
__global__ void __launch_bounds__(256, 2)
gemm_hmma_kernel(const char* __restrict__ imgAh, const char* __restrict__ imgAl,
                 const char* __restrict__ imgNh, const char* __restrict__ imgNl,
                 const char* __restrict__ Bs, const char* __restrict__ Bn,  // hi; lo at +32768
                 const float* __restrict__ bias, float* __restrict__ out,
                 char* __restrict__ oImgH, char* __restrict__ oImgL,
                 int relu, int write_img) {
    extern __shared__ char dyn_smem[];
    uint32_t sbase = (smem_u32(dyn_smem) + 127u) & ~127u;

    const int tid = threadIdx.x;
    const int wid = tid >> 5;
    const int lane = tid & 31;
    const int tile = blockIdx.x;
    const int m0 = tile * 128;
    const int wm = (wid >> 2) * 64;
    const int wn = (wid & 3) * 32;

    // 12 phases: p = part*6 + c*2 + kc. chain c: (Ah,Bh),(Ah,Bl),(Al,Bh).
    const char* srcA[12];
    const char* srcB[12];
    {
        const char* Ahi[2] = {imgAh + (size_t)tile * 32768, imgNh + (size_t)tile * 32768};
        const char* Alo[2] = {imgAl + (size_t)tile * 32768, imgNl + (size_t)tile * 32768};
        const char* Bhi[2] = {Bs, Bn};
        const char* Blo[2] = {Bs + 32768, Bn + 32768};
        #pragma unroll
        for (int part = 0; part < 2; ++part)
            #pragma unroll
            for (int c = 0; c < 3; ++c)
                #pragma unroll
                for (int kc = 0; kc < 2; ++kc) {
                    int p = part * 6 + c * 2 + kc;
                    srcA[p] = (c == 2 ? Alo[part] : Ahi[part]) + kc * 16384;
                    srcB[p] = (c == 1 ? Blo[part] : Bhi[part]) + kc * 16384;
                }
    }

    // stage phase p into buffer b (32KB: A 16KB | B 16KB)
    auto stage = [&](int p, int b) {
        uint32_t sb = sbase + (uint32_t)b * 32768u;
        #pragma unroll
        for (int i = 0; i < 4; ++i) {
            uint32_t o = (uint32_t)(tid + i * 256) * 16u;
            cp_async16(sb + o, srcA[p] + o);
            cp_async16(sb + 16384 + o, srcB[p] + o);
        }
        CP_COMMIT();
    };

    float acc[4][4][4];
    #pragma unroll
    for (int i = 0; i < 4; i++)
        #pragma unroll
        for (int j = 0; j < 4; j++)
            #pragma unroll
            for (int r = 0; r < 4; r++) acc[i][j][r] = 0.f;

    stage(0, 0);
    stage(1, 1);

    #pragma unroll 1
    for (int p = 0; p < 12; ++p) {
        if (p < 10) { stage(p + 2, (p + 2) % 3); CP_WAIT(2); }
        else if (p == 10) { CP_WAIT(1); }
        else { CP_WAIT(0); }
        __syncthreads();

        uint32_t sb = sbase + (uint32_t)(p % 3) * 32768u;
        const uint32_t sA = sb, sB = sb + 16384;
        #pragma unroll
        for (int ks = 0; ks < 4; ++ks) {
            uint32_t a[4][4];
            #pragma unroll
            for (int i = 0; i < 4; ++i) {
                uint32_t row = wm + i * 16 + (lane & 15);
                uint32_t kbyte = ks * 32 + ((lane >> 4) << 4);
                ldsm_x4(sA + swz(row, kbyte), a[i][0], a[i][1], a[i][2], a[i][3]);
            }
            uint32_t b[4][2];
            #pragma unroll
            for (int jj = 0; jj < 2; ++jj) {
                uint32_t mi = (uint32_t)lane >> 3;
                uint32_t row = wn + jj * 16 + ((mi >> 1) << 3) + (lane & 7);
                uint32_t kbyte = ks * 32 + ((mi & 1) << 4);
                uint32_t r0, r1, r2, r3;
                ldsm_x4(sB + swz(row, kbyte), r0, r1, r2, r3);
                b[jj * 2 + 0][0] = r0; b[jj * 2 + 0][1] = r1;
                b[jj * 2 + 1][0] = r2; b[jj * 2 + 1][1] = r3;
            }
            #pragma unroll
            for (int i = 0; i < 4; ++i)
                #pragma unroll
                for (int j = 0; j < 4; ++j)
                    mma_16816(acc[i][j], a[i], b[j]);
        }
        __syncthreads();   // all warps done reading buf before it is restaged
    }

    // ---- epilogue: bias + relu; next-layer images OR final fp32 out ----
    #pragma unroll
    for (int i = 0; i < 4; ++i) {
        int rloc0 = wm + i * 16 + (lane >> 2);
        int r0 = m0 + rloc0;
        #pragma unroll
        for (int j = 0; j < 4; ++j) {
            int col = wn + j * 8 + (lane & 3) * 2;
            float bx = bias[col], by = bias[col + 1];
            float2 v0 = make_float2(acc[i][j][0] + bx, acc[i][j][1] + by);
            float2 v1 = make_float2(acc[i][j][2] + bx, acc[i][j][3] + by);
            if (relu) {
                v0.x = fmaxf(v0.x, 0.f); v0.y = fmaxf(v0.y, 0.f);
                v1.x = fmaxf(v1.x, 0.f); v1.y = fmaxf(v1.y, 0.f);
            }
            if (write_img) {
                uint32_t obase = (uint32_t)tile * 32768u + (uint32_t)(col >> 6) * 16384u;
                uint32_t kb = (uint32_t)((col & 63) * 2);
                uint32_t hp, lp;
                if (r0 < N_NODES) {
                    split2(v0.x, v0.y, hp, lp);
                    uint32_t off = obase + swz((uint32_t)rloc0, kb);
                    *(uint32_t*)(oImgH + off) = hp;
                    *(uint32_t*)(oImgL + off) = lp;
                }
                if (r0 + 8 < N_NODES) {
                    split2(v1.x, v1.y, hp, lp);
                    uint32_t off = obase + swz((uint32_t)(rloc0 + 8), kb);
                    *(uint32_t*)(oImgH + off) = hp;
                    *(uint32_t*)(oImgL + off) = lp;
                }
            } else {
                if (r0 < N_NODES)
                    *reinterpret_cast<float2*>(out + (size_t)r0 * D + col) = v0;
                if (r0 + 8 < N_NODES)
                    *reinterpret_cast<float2*>(out + (size_t)(r0 + 8) * D + col) = v1;
            }
        }
    }
}

// ==================== launch ====================
extern "C" void kernel_launch(void* const* d_in, const int* in_sizes, int n_in,
                              void* d_out, int out_size) {
    const float* features = (const float*)d_in[0];
    const int* src = (const int*)d_in[1];
    const int* dst = (const int*)d_in[2];
    const float* Ws[3] = {(const float*)d_in[3], (const float*)d_in[6], (const float*)d_in[9]};
    const float* Wn[3] = {(const float*)d_in[4], (const float*)d_in[7], (const float*)d_in[10]};
    const float* bb[3] = {(const float*)d_in[5], (const float*)d_in[8], (const float*)d_in[11]};
    float* out = (float*)d_out;

    void *p_hist, *p_bimg, *p_imgA, *p_imgN;
    cudaGetSymbolAddress(&p_hist, g_hist);
    cudaGetSymbolAddress(&p_bimg, g_Bimg);
    cudaGetSymbolAddress(&p_imgA, g_imgA);
    cudaGetSymbolAddress(&p_imgN, g_imgN);

    char* bimg = (char*)p_bimg;
    auto wimg = [&](int mat) { return bimg + (size_t)mat * 65536; };
    const size_t ISZ = (size_t)NT * 32768;
    char* aimg = (char*)p_imgA;
    auto aimgp = [&](int set, int part) { return aimg + ((size_t)set * 2 + part) * ISZ; };
    char* nimg = (char*)p_imgN;

    const size_t smem_bytes = 3 * 32768 + 128;
    cudaFuncSetAttribute(gemm_hmma_kernel, cudaFuncAttributeMaxDynamicSharedMemorySize,
                         (int)smem_bytes);

    cudaMemsetAsync(p_hist, 0, N_NODES * sizeof(int));
    hist_kernel<<<(N_EDGES + 255) / 256, 256>>>(dst);
    convert_features<<<NT, 256>>>(features, aimgp(0, 0), aimgp(0, 1));
    prep_weights<<<48, 256>>>(Ws[0], Wn[0], Ws[1], Wn[1], Ws[2], Wn[2]);
    scan_local<<<SCAN_BLOCKS, 256>>>();
    scan_blocks<<<1, 256>>>();
    scan_apply<<<SCAN_BLOCKS, 256>>>();
    fill_kernel<<<(N_EDGES + 255) / 256, 256>>>(src, dst);

    for (int l = 0; l < 3; ++l) {
        int rset = l & 1;
        int wset = 1 - rset;
        aggregate_kernel<<<(N_NODES * 32 + 255) / 256, 256>>>(
            aimgp(rset, 0), aimgp(rset, 1), nimg, nimg + ISZ);
        gemm_hmma_kernel<<<NT, 256, smem_bytes>>>(
            aimgp(rset, 0), aimgp(rset, 1), nimg, nimg + ISZ,
            wimg(l * 2 + 0), wimg(l * 2 + 1), bb[l], out,
            aimgp(wset, 0), aimgp(wset, 1), (l < 2) ? 1 : 0, (l < 2) ? 1 : 0);
    }
}

// round 10
// speedup vs baseline: 1.1925x; 1.1925x over previous
#include <cuda_runtime.h>
#include <cuda_bf16.h>
#include <cuda_fp16.h>
#include <cstdint>

#define N_NODES 50000
#define N_EDGES 800000
#define D 128
#define NT 391            // ceil(N_NODES/128)
#define SCAN_BLOCKS 196   // 196*256 = 50176 >= N_NODES

// ==================== scratch (no allocations allowed) ====================
__device__ int g_hist[N_NODES];
__device__ int g_cursor[N_NODES];
__device__ int g_rowstart[N_NODES + 1];
__device__ int g_col[N_EDGES];
__device__ int g_blocksum[SCAN_BLOCKS];
__device__ int g_blockoff[SCAN_BLOCKS];
// pre-swizzled bf16 W^T images: [matrix 0..5][hi=0/lo=1][2 kchunks x 128 x 64]
__device__ __align__(128) __nv_bfloat16 g_Bimg[6][2][D * D];
// node-feature tile images: [set][hi/lo][tile*16384 bf16] (32KB per tile: kc0|kc1)
__device__ __align__(128) __nv_bfloat16 g_imgA[2][2][(size_t)NT * 16384];
// hneigh tile images: [hi/lo]
__device__ __align__(128) __nv_bfloat16 g_imgN[2][(size_t)NT * 16384];
// row-major fp16 copies of h for the gather (ping-pong)
__device__ __align__(128) __half g_h16[2][(size_t)N_NODES * D];

// XOR swizzle: row-major 64 bf16 per row (128B), 8 chunks of 16B, chunk ^= row&7
__device__ __forceinline__ uint32_t swz(uint32_t row, uint32_t kbyte) {
    return row * 128u + ((((kbyte >> 4) ^ (row & 7u)) << 4) | (kbyte & 15u));
}

__device__ __forceinline__ uint32_t smem_u32(const void* p) {
    uint32_t a;
    asm("{ .reg .u64 t; cvta.to.shared.u64 t, %1; cvt.u32.u64 %0, t; }" : "=r"(a) : "l"(p));
    return a;
}
__device__ __forceinline__ void cp_async16(uint32_t saddr, const void* gptr) {
    asm volatile("cp.async.cg.shared.global [%0], [%1], 16;" :: "r"(saddr), "l"(gptr));
}
#define CP_COMMIT() asm volatile("cp.async.commit_group;" ::: "memory")
#define CP_WAIT(n)  asm volatile("cp.async.wait_group %0;" :: "n"(n) : "memory")

__device__ __forceinline__ void ldsm_x4(uint32_t addr, uint32_t& r0, uint32_t& r1,
                                        uint32_t& r2, uint32_t& r3) {
    asm volatile("ldmatrix.sync.aligned.m8n8.x4.shared.b16 {%0,%1,%2,%3}, [%4];"
                 : "=r"(r0), "=r"(r1), "=r"(r2), "=r"(r3) : "r"(addr));
}
__device__ __forceinline__ void mma_16816(float* c, const uint32_t* a, const uint32_t* b) {
    asm volatile(
        "mma.sync.aligned.m16n8k16.row.col.f32.bf16.bf16.f32 "
        "{%0,%1,%2,%3}, {%4,%5,%6,%7}, {%8,%9}, {%0,%1,%2,%3};"
        : "+f"(c[0]), "+f"(c[1]), "+f"(c[2]), "+f"(c[3])
        : "r"(a[0]), "r"(a[1]), "r"(a[2]), "r"(a[3]), "r"(b[0]), "r"(b[1]));
}
// split x,y into packed bf16x2 hi + bf16x2 lo(residual)
__device__ __forceinline__ void split2(float x, float y, uint32_t& hp, uint32_t& lp) {
    __nv_bfloat16 hx = __float2bfloat16(x);
    __nv_bfloat16 hy = __float2bfloat16(y);
    __nv_bfloat16 lx = __float2bfloat16(x - __bfloat162float(hx));
    __nv_bfloat16 ly = __float2bfloat16(y - __bfloat162float(hy));
    hp = (uint32_t)__bfloat16_as_ushort(hx) | ((uint32_t)__bfloat16_as_ushort(hy) << 16);
    lp = (uint32_t)__bfloat16_as_ushort(lx) | ((uint32_t)__bfloat16_as_ushort(ly) << 16);
}
// 4 packed halves -> 4 floats
__device__ __forceinline__ float4 h4_to_f4(uint2 u) {
    __half2 a = *reinterpret_cast<__half2*>(&u.x);
    __half2 b = *reinterpret_cast<__half2*>(&u.y);
    float2 fa = __half22float2(a);
    float2 fb = __half22float2(b);
    return make_float4(fa.x, fa.y, fb.x, fb.y);
}

// ==================== CSR build ====================
__global__ void hist_kernel(const int* __restrict__ dst) {
    int e = blockIdx.x * blockDim.x + threadIdx.x;
    if (e < N_EDGES) atomicAdd(&g_hist[dst[e]], 1);
}

__global__ void scan_local() {
    __shared__ int sh[256];
    int t = threadIdx.x;
    int idx = blockIdx.x * 256 + t;
    int v = (idx < N_NODES) ? g_hist[idx] : 0;
    sh[t] = v;
    __syncthreads();
    #pragma unroll
    for (int off = 1; off < 256; off <<= 1) {
        int x = sh[t];
        int add = (t >= off) ? sh[t - off] : 0;
        __syncthreads();
        sh[t] = x + add;
        __syncthreads();
    }
    if (idx < N_NODES) g_rowstart[idx] = sh[t] - v;
    if (t == 255) g_blocksum[blockIdx.x] = sh[255];
}

__global__ void scan_blocks() {
    __shared__ int sh[256];
    int t = threadIdx.x;
    int v = (t < SCAN_BLOCKS) ? g_blocksum[t] : 0;
    sh[t] = v;
    __syncthreads();
    #pragma unroll
    for (int off = 1; off < 256; off <<= 1) {
        int x = sh[t];
        int add = (t >= off) ? sh[t - off] : 0;
        __syncthreads();
        sh[t] = x + add;
        __syncthreads();
    }
    if (t < SCAN_BLOCKS) g_blockoff[t] = sh[t] - v;
    if (t == 255) g_rowstart[N_NODES] = sh[255];
}

__global__ void scan_apply() {
    int idx = blockIdx.x * 256 + threadIdx.x;
    if (idx < N_NODES) {
        int r = g_rowstart[idx] + g_blockoff[blockIdx.x];
        g_rowstart[idx] = r;
        g_cursor[idx] = r;
    }
}

__global__ void fill_kernel(const int* __restrict__ src, const int* __restrict__ dst) {
    int e = blockIdx.x * blockDim.x + threadIdx.x;
    if (e < N_EDGES) {
        int pos = atomicAdd(&g_cursor[dst[e]], 1);
        g_col[pos] = src[e];
    }
}

// ==================== features fp32 -> tile images + fp16 copy (set 0) ============
__global__ void convert_features(const float* __restrict__ h, char* __restrict__ hi,
                                 char* __restrict__ lo, __half* __restrict__ h16) {
    int tile = blockIdx.x;
    int m0 = tile * 128;
    #pragma unroll 4
    for (int it = 0; it < 32; ++it) {
        int idx = threadIdx.x + it * 256;
        int row = idx >> 6;
        int k = (idx & 63) * 2;
        int gm = m0 + row;
        float2 a = (gm < N_NODES) ? *reinterpret_cast<const float2*>(h + (size_t)gm * D + k)
                                  : make_float2(0.f, 0.f);
        uint32_t hp, lp;
        split2(a.x, a.y, hp, lp);
        uint32_t off = (uint32_t)tile * 32768u + (uint32_t)(k >> 6) * 16384u
                     + swz((uint32_t)row, (uint32_t)((k & 63) * 2));
        *(uint32_t*)(hi + off) = hp;
        *(uint32_t*)(lo + off) = lp;
        if (gm < N_NODES)
            *reinterpret_cast<__half2*>(h16 + (size_t)gm * D + k) = __floats2half2_rn(a.x, a.y);
    }
}

// ==================== aggregation: warp/node, fp16 gather -> hneigh images =========
__global__ void aggregate_kernel(const __half* __restrict__ h16, char* __restrict__ nhi,
                                 char* __restrict__ nlo) {
    int node = (blockIdx.x * blockDim.x + threadIdx.x) >> 5;
    int lane = threadIdx.x & 31;
    if (node >= N_NODES) return;
    int beg = g_rowstart[node];
    int end = g_rowstart[node + 1];
    const int k0 = lane * 4;

    float4 acc = make_float4(0.f, 0.f, 0.f, 0.f);
    int i = beg;
    for (; i + 4 <= end; i += 4) {
        int s0 = g_col[i + 0];
        int s1 = g_col[i + 1];
        int s2 = g_col[i + 2];
        int s3 = g_col[i + 3];
        uint2 u0 = *reinterpret_cast<const uint2*>(h16 + (size_t)s0 * D + k0);
        uint2 u1 = *reinterpret_cast<const uint2*>(h16 + (size_t)s1 * D + k0);
        uint2 u2 = *reinterpret_cast<const uint2*>(h16 + (size_t)s2 * D + k0);
        uint2 u3 = *reinterpret_cast<const uint2*>(h16 + (size_t)s3 * D + k0);
        float4 v0 = h4_to_f4(u0);
        float4 v1 = h4_to_f4(u1);
        float4 v2 = h4_to_f4(u2);
        float4 v3 = h4_to_f4(u3);
        acc.x += (v0.x + v1.x) + (v2.x + v3.x);
        acc.y += (v0.y + v1.y) + (v2.y + v3.y);
        acc.z += (v0.z + v1.z) + (v2.z + v3.z);
        acc.w += (v0.w + v1.w) + (v2.w + v3.w);
    }
    for (; i < end; ++i) {
        int s = g_col[i];
        float4 v = h4_to_f4(*reinterpret_cast<const uint2*>(h16 + (size_t)s * D + k0));
        acc.x += v.x; acc.y += v.y; acc.z += v.z; acc.w += v.w;
    }
    float sc = 1.0f / fmaxf((float)(end - beg), 1.0f);
    acc.x *= sc; acc.y *= sc; acc.z *= sc; acc.w *= sc;

    int tile = node >> 7;
    int row = node & 127;
    uint32_t off = (uint32_t)tile * 32768u + (uint32_t)(k0 >> 6) * 16384u
                 + swz((uint32_t)row, (uint32_t)((k0 & 63) * 2));
    uint32_t h0, l0, h1, l1;
    split2(acc.x, acc.y, h0, l0);
    split2(acc.z, acc.w, h1, l1);
    *(uint2*)(nhi + off) = make_uint2(h0, h1);
    *(uint2*)(nlo + off) = make_uint2(l0, l1);
}

// ==================== weight prep ====================
__global__ void prep_weights(const float* W0s, const float* W0n, const float* W1s,
                             const float* W1n, const float* W2s, const float* W2n) {
    const float* Wp[6] = {W0s, W0n, W1s, W1n, W2s, W2n};
    int mat = blockIdx.x >> 3;
    int sub = blockIdx.x & 7;
    const float* W = Wp[mat];
    char* hi = (char*)g_Bimg[mat][0];
    char* lo = (char*)g_Bimg[mat][1];
    for (int t = threadIdx.x; t < 1024; t += blockDim.x) {
        int idx = sub * 1024 + t;
        int n = idx >> 6;
        int k = (idx & 63) * 2;
        float a0 = W[(size_t)k * D + n];
        float a1 = W[(size_t)(k + 1) * D + n];
        uint32_t hp, lp;
        split2(a0, a1, hp, lp);
        uint32_t off = (uint32_t)(k >> 6) * 16384u + swz((uint32_t)n, (uint32_t)((k & 63) * 2));
        *(uint32_t*)(hi + off) = hp;
        *(uint32_t*)(lo + off) = lp;
    }
}

// ==================== HMMA dual GEMM, 12x32KB phases, double-buffered, occ=2 =======
__global__ void __launch_bounds__(256, 2)
gemm_hmma_kernel(const char* __restrict__ imgAh, const char* __restrict__ imgAl,
                 const char* __restrict__ imgNh, const char* __restrict__ imgNl,
                 const char* __restrict__ Bs, const char* __restrict__ Bn,  // hi; lo at +32768
                 const float* __restrict__ bias, float* __restrict__ out,
                 char* __restrict__ oImgH, char* __restrict__ oImgL,
                 __half* __restrict__ oH16,
                 int relu, int write_img) {
    extern __shared__ char dyn_smem[];
    uint32_t sbase = (smem_u32(dyn_smem) + 127u) & ~127u;

    const int tid = threadIdx.x;
    const int wid = tid >> 5;
    const int lane = tid & 31;
    const int tile = blockIdx.x;
    const int m0 = tile * 128;
    const int wm = (wid >> 2) * 64;
    const int wn = (wid & 3) * 32;

    // 12 phases: p = part*6 + c*2 + kc. chain c: (Ah,Bh),(Ah,Bl),(Al,Bh).
    const char* srcA[12];
    const char* srcB[12];
    {
        const char* Ahi[2] = {imgAh + (size_t)tile * 32768, imgNh + (size_t)tile * 32768};
        const char* Alo[2] = {imgAl + (size_t)tile * 32768, imgNl + (size_t)tile * 32768};
        const char* Bhi[2] = {Bs, Bn};
        const char* Blo[2] = {Bs + 32768, Bn + 32768};
        #pragma unroll
        for (int part = 0; part < 2; ++part)
            #pragma unroll
            for (int c = 0; c < 3; ++c)
                #pragma unroll
                for (int kc = 0; kc < 2; ++kc) {
                    int p = part * 6 + c * 2 + kc;
                    srcA[p] = (c == 2 ? Alo[part] : Ahi[part]) + kc * 16384;
                    srcB[p] = (c == 1 ? Blo[part] : Bhi[part]) + kc * 16384;
                }
    }

    // stage phase p into buffer b (32KB: A 16KB | B 16KB)
    auto stage = [&](int p, int b) {
        uint32_t sb = sbase + (uint32_t)b * 32768u;
        #pragma unroll
        for (int i = 0; i < 4; ++i) {
            uint32_t o = (uint32_t)(tid + i * 256) * 16u;
            cp_async16(sb + o, srcA[p] + o);
            cp_async16(sb + 16384 + o, srcB[p] + o);
        }
        CP_COMMIT();
    };

    float acc[4][4][4];
    #pragma unroll
    for (int i = 0; i < 4; i++)
        #pragma unroll
        for (int j = 0; j < 4; j++)
            #pragma unroll
            for (int r = 0; r < 4; r++) acc[i][j][r] = 0.f;

    stage(0, 0);

    #pragma unroll 1
    for (int p = 0; p < 12; ++p) {
        if (p < 11) stage(p + 1, (p + 1) & 1);
        if (p < 11) { CP_WAIT(1); } else { CP_WAIT(0); }
        __syncthreads();

        uint32_t sb = sbase + (uint32_t)(p & 1) * 32768u;
        const uint32_t sA = sb, sB = sb + 16384;
        #pragma unroll
        for (int ks = 0; ks < 4; ++ks) {
            uint32_t a[4][4];
            #pragma unroll
            for (int i = 0; i < 4; ++i) {
                uint32_t row = wm + i * 16 + (lane & 15);
                uint32_t kbyte = ks * 32 + ((lane >> 4) << 4);
                ldsm_x4(sA + swz(row, kbyte), a[i][0], a[i][1], a[i][2], a[i][3]);
            }
            uint32_t b[4][2];
            #pragma unroll
            for (int jj = 0; jj < 2; ++jj) {
                uint32_t mi = (uint32_t)lane >> 3;
                uint32_t row = wn + jj * 16 + ((mi >> 1) << 3) + (lane & 7);
                uint32_t kbyte = ks * 32 + ((mi & 1) << 4);
                uint32_t r0, r1, r2, r3;
                ldsm_x4(sB + swz(row, kbyte), r0, r1, r2, r3);
                b[jj * 2 + 0][0] = r0; b[jj * 2 + 0][1] = r1;
                b[jj * 2 + 1][0] = r2; b[jj * 2 + 1][1] = r3;
            }
            #pragma unroll
            for (int i = 0; i < 4; ++i)
                #pragma unroll
                for (int j = 0; j < 4; ++j)
                    mma_16816(acc[i][j], a[i], b[j]);
        }
        __syncthreads();   // all warps done reading buf before stage(p+2) overwrites it
    }

    // ---- epilogue: bias + relu; next-layer images+fp16 OR final fp32 out ----
    #pragma unroll
    for (int i = 0; i < 4; ++i) {
        int rloc0 = wm + i * 16 + (lane >> 2);
        int r0 = m0 + rloc0;
        #pragma unroll
        for (int j = 0; j < 4; ++j) {
            int col = wn + j * 8 + (lane & 3) * 2;
            float bx = bias[col], by = bias[col + 1];
            float2 v0 = make_float2(acc[i][j][0] + bx, acc[i][j][1] + by);
            float2 v1 = make_float2(acc[i][j][2] + bx, acc[i][j][3] + by);
            if (relu) {
                v0.x = fmaxf(v0.x, 0.f); v0.y = fmaxf(v0.y, 0.f);
                v1.x = fmaxf(v1.x, 0.f); v1.y = fmaxf(v1.y, 0.f);
            }
            if (write_img) {
                uint32_t obase = (uint32_t)tile * 32768u + (uint32_t)(col >> 6) * 16384u;
                uint32_t kb = (uint32_t)((col & 63) * 2);
                uint32_t hp, lp;
                if (r0 < N_NODES) {
                    split2(v0.x, v0.y, hp, lp);
                    uint32_t off = obase + swz((uint32_t)rloc0, kb);
                    *(uint32_t*)(oImgH + off) = hp;
                    *(uint32_t*)(oImgL + off) = lp;
                    *reinterpret_cast<__half2*>(oH16 + (size_t)r0 * D + col) =
                        __floats2half2_rn(v0.x, v0.y);
                }
                if (r0 + 8 < N_NODES) {
                    split2(v1.x, v1.y, hp, lp);
                    uint32_t off = obase + swz((uint32_t)(rloc0 + 8), kb);
                    *(uint32_t*)(oImgH + off) = hp;
                    *(uint32_t*)(oImgL + off) = lp;
                    *reinterpret_cast<__half2*>(oH16 + (size_t)(r0 + 8) * D + col) =
                        __floats2half2_rn(v1.x, v1.y);
                }
            } else {
                if (r0 < N_NODES)
                    *reinterpret_cast<float2*>(out + (size_t)r0 * D + col) = v0;
                if (r0 + 8 < N_NODES)
                    *reinterpret_cast<float2*>(out + (size_t)(r0 + 8) * D + col) = v1;
            }
        }
    }
}

// ==================== launch ====================
extern "C" void kernel_launch(void* const* d_in, const int* in_sizes, int n_in,
                              void* d_out, int out_size) {
    const float* features = (const float*)d_in[0];
    const int* src = (const int*)d_in[1];
    const int* dst = (const int*)d_in[2];
    const float* Ws[3] = {(const float*)d_in[3], (const float*)d_in[6], (const float*)d_in[9]};
    const float* Wn[3] = {(const float*)d_in[4], (const float*)d_in[7], (const float*)d_in[10]};
    const float* bb[3] = {(const float*)d_in[5], (const float*)d_in[8], (const float*)d_in[11]};
    float* out = (float*)d_out;

    void *p_hist, *p_bimg, *p_imgA, *p_imgN, *p_h16;
    cudaGetSymbolAddress(&p_hist, g_hist);
    cudaGetSymbolAddress(&p_bimg, g_Bimg);
    cudaGetSymbolAddress(&p_imgA, g_imgA);
    cudaGetSymbolAddress(&p_imgN, g_imgN);
    cudaGetSymbolAddress(&p_h16, g_h16);

    char* bimg = (char*)p_bimg;
    auto wimg = [&](int mat) { return bimg + (size_t)mat * 65536; };
    const size_t ISZ = (size_t)NT * 32768;
    char* aimg = (char*)p_imgA;
    auto aimgp = [&](int set, int part) { return aimg + ((size_t)set * 2 + part) * ISZ; };
    char* nimg = (char*)p_imgN;
    __half* h16 = (__half*)p_h16;
    auto h16p = [&](int set) { return h16 + (size_t)set * N_NODES * D; };

    const size_t smem_bytes = 2 * 32768 + 128;
    cudaFuncSetAttribute(gemm_hmma_kernel, cudaFuncAttributeMaxDynamicSharedMemorySize,
                         (int)smem_bytes);

    cudaMemsetAsync(p_hist, 0, N_NODES * sizeof(int));
    hist_kernel<<<(N_EDGES + 255) / 256, 256>>>(dst);
    convert_features<<<NT, 256>>>(features, aimgp(0, 0), aimgp(0, 1), h16p(0));
    prep_weights<<<48, 256>>>(Ws[0], Wn[0], Ws[1], Wn[1], Ws[2], Wn[2]);
    scan_local<<<SCAN_BLOCKS, 256>>>();
    scan_blocks<<<1, 256>>>();
    scan_apply<<<SCAN_BLOCKS, 256>>>();
    fill_kernel<<<(N_EDGES + 255) / 256, 256>>>(src, dst);

    for (int l = 0; l < 3; ++l) {
        int rset = l & 1;            // 0,1,0
        int wset = 1 - rset;
        aggregate_kernel<<<(N_NODES * 32 + 255) / 256, 256>>>(
            h16p(rset), nimg, nimg + ISZ);
        gemm_hmma_kernel<<<NT, 256, smem_bytes>>>(
            aimgp(rset, 0), aimgp(rset, 1), nimg, nimg + ISZ,
            wimg(l * 2 + 0), wimg(l * 2 + 1), bb[l], out,
            aimgp(wset, 0), aimgp(wset, 1), h16p(wset),
            (l < 2) ? 1 : 0, (l < 2) ? 1 : 0);
    }
}

// round 11
// speedup vs baseline: 1.7839x; 1.4959x over previous
#include <cuda_runtime.h>
#include <cuda_fp16.h>
#include <cstdint>

#define N_NODES 50000
#define N_EDGES 800000
#define D 128
#define NT 391            // ceil(N_NODES/128)
#define SCAN_BLOCKS 196   // 196*256 = 50176 >= N_NODES

// ==================== scratch (no allocations allowed) ====================
__device__ int g_hist[N_NODES];
__device__ int g_cursor[N_NODES];
__device__ int g_rowstart[N_NODES + 1];
__device__ int g_col[N_EDGES];
__device__ int g_blocksum[SCAN_BLOCKS];
__device__ int g_blockoff[SCAN_BLOCKS];
// fp16 swizzled weight images: [matrix 0..5][2 kchunks x 128 x 64]
__device__ __align__(128) __half g_Wimg[6][D * D];
// fp16 swizzled h tile images (ping-pong sets)
__device__ __align__(128) __half g_img[2][(size_t)NT * 16384];
// fp16 swizzled hneigh tile image
__device__ __align__(128) __half g_imgN[(size_t)NT * 16384];

// XOR swizzle: row-major 64 fp16 per row (128B), 8 chunks of 16B, chunk ^= row&7
__device__ __forceinline__ uint32_t swz(uint32_t row, uint32_t kbyte) {
    return row * 128u + ((((kbyte >> 4) ^ (row & 7u)) << 4) | (kbyte & 15u));
}

__device__ __forceinline__ uint32_t smem_u32(const void* p) {
    uint32_t a;
    asm("{ .reg .u64 t; cvta.to.shared.u64 t, %1; cvt.u32.u64 %0, t; }" : "=r"(a) : "l"(p));
    return a;
}
__device__ __forceinline__ void cp_async16(uint32_t saddr, const void* gptr) {
    asm volatile("cp.async.cg.shared.global [%0], [%1], 16;" :: "r"(saddr), "l"(gptr));
}
#define CP_COMMIT() asm volatile("cp.async.commit_group;" ::: "memory")
#define CP_WAIT(n)  asm volatile("cp.async.wait_group %0;" :: "n"(n) : "memory")

__device__ __forceinline__ void ldsm_x4(uint32_t addr, uint32_t& r0, uint32_t& r1,
                                        uint32_t& r2, uint32_t& r3) {
    asm volatile("ldmatrix.sync.aligned.m8n8.x4.shared.b16 {%0,%1,%2,%3}, [%4];"
                 : "=r"(r0), "=r"(r1), "=r"(r2), "=r"(r3) : "r"(addr));
}
__device__ __forceinline__ void mma_16816(float* c, const uint32_t* a, const uint32_t* b) {
    asm volatile(
        "mma.sync.aligned.m16n8k16.row.col.f32.f16.f16.f32 "
        "{%0,%1,%2,%3}, {%4,%5,%6,%7}, {%8,%9}, {%0,%1,%2,%3};"
        : "+f"(c[0]), "+f"(c[1]), "+f"(c[2]), "+f"(c[3])
        : "r"(a[0]), "r"(a[1]), "r"(a[2]), "r"(a[3]), "r"(b[0]), "r"(b[1]));
}
// 4 packed halves -> 4 floats
__device__ __forceinline__ float4 h4_to_f4(uint2 u) {
    __half2 a = *reinterpret_cast<__half2*>(&u.x);
    __half2 b = *reinterpret_cast<__half2*>(&u.y);
    float2 fa = __half22float2(a);
    float2 fb = __half22float2(b);
    return make_float4(fa.x, fa.y, fb.x, fb.y);
}
__device__ __forceinline__ uint32_t pack_h2(float x, float y) {
    __half2 h = __floats2half2_rn(x, y);
    return *reinterpret_cast<uint32_t*>(&h);
}

// ==================== CSR build ====================
__global__ void hist_kernel(const int* __restrict__ dst) {
    int e = blockIdx.x * blockDim.x + threadIdx.x;
    if (e < N_EDGES) atomicAdd(&g_hist[dst[e]], 1);
}

__global__ void scan_local() {
    __shared__ int sh[256];
    int t = threadIdx.x;
    int idx = blockIdx.x * 256 + t;
    int v = (idx < N_NODES) ? g_hist[idx] : 0;
    sh[t] = v;
    __syncthreads();
    #pragma unroll
    for (int off = 1; off < 256; off <<= 1) {
        int x = sh[t];
        int add = (t >= off) ? sh[t - off] : 0;
        __syncthreads();
        sh[t] = x + add;
        __syncthreads();
    }
    if (idx < N_NODES) g_rowstart[idx] = sh[t] - v;
    if (t == 255) g_blocksum[blockIdx.x] = sh[255];
}

__global__ void scan_blocks() {
    __shared__ int sh[256];
    int t = threadIdx.x;
    int v = (t < SCAN_BLOCKS) ? g_blocksum[t] : 0;
    sh[t] = v;
    __syncthreads();
    #pragma unroll
    for (int off = 1; off < 256; off <<= 1) {
        int x = sh[t];
        int add = (t >= off) ? sh[t - off] : 0;
        __syncthreads();
        sh[t] = x + add;
        __syncthreads();
    }
    if (t < SCAN_BLOCKS) g_blockoff[t] = sh[t] - v;
    if (t == 255) g_rowstart[N_NODES] = sh[255];
}

__global__ void scan_apply() {
    int idx = blockIdx.x * 256 + threadIdx.x;
    if (idx < N_NODES) {
        int r = g_rowstart[idx] + g_blockoff[blockIdx.x];
        g_rowstart[idx] = r;
        g_cursor[idx] = r;
    }
}

__global__ void fill_kernel(const int* __restrict__ src, const int* __restrict__ dst) {
    int e = blockIdx.x * blockDim.x + threadIdx.x;
    if (e < N_EDGES) {
        int pos = atomicAdd(&g_cursor[dst[e]], 1);
        g_col[pos] = src[e];
    }
}

// ==================== features fp32 -> fp16 tile image (set 0) ====================
__global__ void convert_features(const float* __restrict__ h, char* __restrict__ img) {
    int tile = blockIdx.x;
    int m0 = tile * 128;
    #pragma unroll 4
    for (int it = 0; it < 32; ++it) {
        int idx = threadIdx.x + it * 256;   // 0..8191 (row, kpair)
        int row = idx >> 6;
        int k = (idx & 63) * 2;
        int gm = m0 + row;
        float2 a = (gm < N_NODES) ? *reinterpret_cast<const float2*>(h + (size_t)gm * D + k)
                                  : make_float2(0.f, 0.f);
        uint32_t off = (uint32_t)tile * 32768u + (uint32_t)(k >> 6) * 16384u
                     + swz((uint32_t)row, (uint32_t)((k & 63) * 2));
        *(uint32_t*)(img + off) = pack_h2(a.x, a.y);
    }
}

// ==================== aggregation: warp/node, gathers fp16 image -> fp16 image =====
__global__ void aggregate_kernel(const char* __restrict__ img, char* __restrict__ nimg) {
    int node = (blockIdx.x * blockDim.x + threadIdx.x) >> 5;
    int lane = threadIdx.x & 31;
    if (node >= N_NODES) return;
    int beg = g_rowstart[node];
    int end = g_rowstart[node + 1];

    const int k0 = lane * 4;                                  // features k0..k0+3
    const uint32_t laneoff = (uint32_t)(k0 >> 6) * 16384u;    // k-chunk select
    const uint32_t kb = (uint32_t)((k0 & 63) * 2);            // byte within row

    float4 acc = make_float4(0.f, 0.f, 0.f, 0.f);
    int i = beg;
    for (; i + 4 <= end; i += 4) {
        int s0 = g_col[i + 0];
        int s1 = g_col[i + 1];
        int s2 = g_col[i + 2];
        int s3 = g_col[i + 3];
        uint32_t o0 = (uint32_t)(s0 >> 7) * 32768u + laneoff + swz((uint32_t)(s0 & 127), kb);
        uint32_t o1 = (uint32_t)(s1 >> 7) * 32768u + laneoff + swz((uint32_t)(s1 & 127), kb);
        uint32_t o2 = (uint32_t)(s2 >> 7) * 32768u + laneoff + swz((uint32_t)(s2 & 127), kb);
        uint32_t o3 = (uint32_t)(s3 >> 7) * 32768u + laneoff + swz((uint32_t)(s3 & 127), kb);
        float4 v0 = h4_to_f4(*(const uint2*)(img + o0));
        float4 v1 = h4_to_f4(*(const uint2*)(img + o1));
        float4 v2 = h4_to_f4(*(const uint2*)(img + o2));
        float4 v3 = h4_to_f4(*(const uint2*)(img + o3));
        acc.x += (v0.x + v1.x) + (v2.x + v3.x);
        acc.y += (v0.y + v1.y) + (v2.y + v3.y);
        acc.z += (v0.z + v1.z) + (v2.z + v3.z);
        acc.w += (v0.w + v1.w) + (v2.w + v3.w);
    }
    for (; i < end; ++i) {
        int s = g_col[i];
        uint32_t o = (uint32_t)(s >> 7) * 32768u + laneoff + swz((uint32_t)(s & 127), kb);
        float4 v = h4_to_f4(*(const uint2*)(img + o));
        acc.x += v.x; acc.y += v.y; acc.z += v.z; acc.w += v.w;
    }
    float sc = 1.0f / fmaxf((float)(end - beg), 1.0f);

    int tile = node >> 7;
    int row = node & 127;
    uint32_t off = (uint32_t)tile * 32768u + laneoff + swz((uint32_t)row, kb);
    uint2 o2v;
    o2v.x = pack_h2(acc.x * sc, acc.y * sc);
    o2v.y = pack_h2(acc.z * sc, acc.w * sc);
    *(uint2*)(nimg + off) = o2v;
}

// ==================== weight prep: W[k][n] -> fp16 swizzled W^T image ====
__global__ void prep_weights(const float* W0s, const float* W0n, const float* W1s,
                             const float* W1n, const float* W2s, const float* W2n) {
    const float* Wp[6] = {W0s, W0n, W1s, W1n, W2s, W2n};
    int mat = blockIdx.x >> 3;
    int sub = blockIdx.x & 7;
    const float* W = Wp[mat];
    char* img = (char*)g_Wimg[mat];
    for (int t = threadIdx.x; t < 1024; t += blockDim.x) {
        int idx = sub * 1024 + t;          // 0..8191
        int n = idx >> 6;
        int k = (idx & 63) * 2;
        float a0 = W[(size_t)k * D + n];
        float a1 = W[(size_t)(k + 1) * D + n];
        uint32_t off = (uint32_t)(k >> 6) * 16384u + swz((uint32_t)n, (uint32_t)((k & 63) * 2));
        *(uint32_t*)(img + off) = pack_h2(a0, a1);
    }
}

// ==================== HMMA dual GEMM, fp16 single-pass, 4x32KB phases ==============
__global__ void __launch_bounds__(256, 2)
gemm_hmma_kernel(const char* __restrict__ imgA, const char* __restrict__ imgN,
                 const char* __restrict__ Bs, const char* __restrict__ Bn,
                 const float* __restrict__ bias, float* __restrict__ out,
                 char* __restrict__ oImg, int relu, int write_img) {
    extern __shared__ char dyn_smem[];
    uint32_t sbase = (smem_u32(dyn_smem) + 127u) & ~127u;

    const int tid = threadIdx.x;
    const int wid = tid >> 5;
    const int lane = tid & 31;
    const int tile = blockIdx.x;
    const int m0 = tile * 128;
    const int wm = (wid >> 2) * 64;
    const int wn = (wid & 3) * 32;

    // 4 phases: p = part*2 + kc
    const char* srcA[4];
    const char* srcB[4];
    {
        const char* A0 = imgA + (size_t)tile * 32768;
        const char* N0 = imgN + (size_t)tile * 32768;
        #pragma unroll
        for (int kc = 0; kc < 2; ++kc) {
            srcA[kc] = A0 + kc * 16384;      srcB[kc] = Bs + kc * 16384;
            srcA[2 + kc] = N0 + kc * 16384;  srcB[2 + kc] = Bn + kc * 16384;
        }
    }

    // stage phase p into buffer b (32KB: A 16KB | B 16KB)
    auto stage = [&](int p, int b) {
        uint32_t sb = sbase + (uint32_t)b * 32768u;
        #pragma unroll
        for (int i = 0; i < 4; ++i) {
            uint32_t o = (uint32_t)(tid + i * 256) * 16u;
            cp_async16(sb + o, srcA[p] + o);
            cp_async16(sb + 16384 + o, srcB[p] + o);
        }
        CP_COMMIT();
    };

    float acc[4][4][4];
    #pragma unroll
    for (int i = 0; i < 4; i++)
        #pragma unroll
        for (int j = 0; j < 4; j++)
            #pragma unroll
            for (int r = 0; r < 4; r++) acc[i][j][r] = 0.f;

    stage(0, 0);

    #pragma unroll 1
    for (int p = 0; p < 4; ++p) {
        if (p < 3) { stage(p + 1, (p + 1) & 1); CP_WAIT(1); }
        else       { CP_WAIT(0); }
        __syncthreads();

        uint32_t sb = sbase + (uint32_t)(p & 1) * 32768u;
        const uint32_t sA = sb, sB = sb + 16384;
        #pragma unroll
        for (int ks = 0; ks < 4; ++ks) {
            uint32_t a[4][4];
            #pragma unroll
            for (int i = 0; i < 4; ++i) {
                uint32_t row = wm + i * 16 + (lane & 15);
                uint32_t kbyte = ks * 32 + ((lane >> 4) << 4);
                ldsm_x4(sA + swz(row, kbyte), a[i][0], a[i][1], a[i][2], a[i][3]);
            }
            uint32_t b[4][2];
            #pragma unroll
            for (int jj = 0; jj < 2; ++jj) {
                uint32_t mi = (uint32_t)lane >> 3;
                uint32_t row = wn + jj * 16 + ((mi >> 1) << 3) + (lane & 7);
                uint32_t kbyte = ks * 32 + ((mi & 1) << 4);
                uint32_t r0, r1, r2, r3;
                ldsm_x4(sB + swz(row, kbyte), r0, r1, r2, r3);
                b[jj * 2 + 0][0] = r0; b[jj * 2 + 0][1] = r1;
                b[jj * 2 + 1][0] = r2; b[jj * 2 + 1][1] = r3;
            }
            #pragma unroll
            for (int i = 0; i < 4; ++i)
                #pragma unroll
                for (int j = 0; j < 4; ++j)
                    mma_16816(acc[i][j], a[i], b[j]);
        }
        __syncthreads();   // all warps done reading buf before restage
    }

    // ---- epilogue: bias + relu; fp16 next-layer image OR final fp32 out ----
    #pragma unroll
    for (int i = 0; i < 4; ++i) {
        int rloc0 = wm + i * 16 + (lane >> 2);
        int r0 = m0 + rloc0;
        #pragma unroll
        for (int j = 0; j < 4; ++j) {
            int col = wn + j * 8 + (lane & 3) * 2;
            float bx = bias[col], by = bias[col + 1];
            float2 v0 = make_float2(acc[i][j][0] + bx, acc[i][j][1] + by);
            float2 v1 = make_float2(acc[i][j][2] + bx, acc[i][j][3] + by);
            if (relu) {
                v0.x = fmaxf(v0.x, 0.f); v0.y = fmaxf(v0.y, 0.f);
                v1.x = fmaxf(v1.x, 0.f); v1.y = fmaxf(v1.y, 0.f);
            }
            if (write_img) {
                uint32_t obase = (uint32_t)tile * 32768u + (uint32_t)(col >> 6) * 16384u;
                uint32_t kb = (uint32_t)((col & 63) * 2);
                if (r0 < N_NODES)
                    *(uint32_t*)(oImg + obase + swz((uint32_t)rloc0, kb)) = pack_h2(v0.x, v0.y);
                if (r0 + 8 < N_NODES)
                    *(uint32_t*)(oImg + obase + swz((uint32_t)(rloc0 + 8), kb)) = pack_h2(v1.x, v1.y);
            } else {
                if (r0 < N_NODES)
                    *reinterpret_cast<float2*>(out + (size_t)r0 * D + col) = v0;
                if (r0 + 8 < N_NODES)
                    *reinterpret_cast<float2*>(out + (size_t)(r0 + 8) * D + col) = v1;
            }
        }
    }
}

// ==================== launch ====================
extern "C" void kernel_launch(void* const* d_in, const int* in_sizes, int n_in,
                              void* d_out, int out_size) {
    const float* features = (const float*)d_in[0];
    const int* src = (const int*)d_in[1];
    const int* dst = (const int*)d_in[2];
    const float* Ws[3] = {(const float*)d_in[3], (const float*)d_in[6], (const float*)d_in[9]};
    const float* Wn[3] = {(const float*)d_in[4], (const float*)d_in[7], (const float*)d_in[10]};
    const float* bb[3] = {(const float*)d_in[5], (const float*)d_in[8], (const float*)d_in[11]};
    float* out = (float*)d_out;

    void *p_hist, *p_wimg, *p_img, *p_imgN;
    cudaGetSymbolAddress(&p_hist, g_hist);
    cudaGetSymbolAddress(&p_wimg, g_Wimg);
    cudaGetSymbolAddress(&p_img, g_img);
    cudaGetSymbolAddress(&p_imgN, g_imgN);

    char* wimg = (char*)p_wimg;
    auto wimgp = [&](int mat) { return wimg + (size_t)mat * 32768; };
    const size_t ISZ = (size_t)NT * 32768;   // bytes per h image
    char* himg = (char*)p_img;
    auto himgp = [&](int set) { return himg + (size_t)set * ISZ; };
    char* nimg = (char*)p_imgN;

    const size_t smem_bytes = 2 * 32768 + 128;
    cudaFuncSetAttribute(gemm_hmma_kernel, cudaFuncAttributeMaxDynamicSharedMemorySize,
                         (int)smem_bytes);

    cudaMemsetAsync(p_hist, 0, N_NODES * sizeof(int));
    hist_kernel<<<(N_EDGES + 255) / 256, 256>>>(dst);
    convert_features<<<NT, 256>>>(features, himgp(0));
    prep_weights<<<48, 256>>>(Ws[0], Wn[0], Ws[1], Wn[1], Ws[2], Wn[2]);
    scan_local<<<SCAN_BLOCKS, 256>>>();
    scan_blocks<<<1, 256>>>();
    scan_apply<<<SCAN_BLOCKS, 256>>>();
    fill_kernel<<<(N_EDGES + 255) / 256, 256>>>(src, dst);

    for (int l = 0; l < 3; ++l) {
        int rset = l & 1;            // 0,1,0
        int wset = 1 - rset;
        aggregate_kernel<<<(N_NODES * 32 + 255) / 256, 256>>>(himgp(rset), nimg);
        gemm_hmma_kernel<<<NT, 256, smem_bytes>>>(
            himgp(rset), nimg, wimgp(l * 2 + 0), wimgp(l * 2 + 1),
            bb[l], out, himgp(wset), (l < 2) ? 1 : 0, (l < 2) ? 1 : 0);
    }
}